// round 2
// baseline (speedup 1.0000x reference)
#include <cuda_runtime.h>
#include <cstdint>

// ---------------------------------------------------------------------------
// GATGraphSimilarity: Siamese 2-layer GAT (heads=4 then 1) + mean pool
// N=50000, E=800000 (+N self loops), IN=128, HID=64, G=64 graphs per batch.
// All scratch in __device__ globals (no allocation). fp32 SIMT everywhere.
// NOTE: edge_index / batch are int32 on device (JAX x64 disabled).
// ---------------------------------------------------------------------------

#define NMAX 50000
#define GNUM 64
#define NEG_SLOPE 0.2f

__device__ float g_H   [(size_t)NMAX * 256];  // conv1 pre-aggregation features
__device__ float g_OUT [(size_t)NMAX * 256];  // conv1 output (elu'd) = conv2 input
__device__ float g_H2  [(size_t)NMAX * 64];   // conv2 pre-aggregation features
__device__ float g_OUT2[(size_t)NMAX * 64];   // conv2 output
__device__ float g_AS  [NMAX * 4];
__device__ float g_AD  [NMAX * 4];
__device__ float g_MAX [NMAX * 4];
__device__ float g_DEN [NMAX * 4];
__device__ float g_POOL[2 * GNUM * 64];
__device__ float g_CNT [2 * GNUM];

static inline int cdiv(int a, int b) { return (a + b - 1) / b; }

__device__ __forceinline__ float leaky(float v) {
    return v > 0.0f ? v : NEG_SLOPE * v;
}

__device__ __forceinline__ void atomicMaxF(float* addr, float val) {
    float old = *addr;
    while (old < val) {
        int assumed = __float_as_int(old);
        int prev = atomicCAS((int*)addr, assumed, __float_as_int(val));
        if (prev == assumed) break;
        old = __int_as_float(prev);
    }
}

// ---------------------------------------------------------------------------
// SGEMM: C[M, Nc] = A[M, K] @ B[K, Nc].  Nc multiple of 64, K multiple of 16.
// 64x64 block tile, 256 threads, 4x4 register micro-tile.
// ---------------------------------------------------------------------------
__global__ void sgemm_kernel(const float* __restrict__ A,
                             const float* __restrict__ B,
                             float* __restrict__ C,
                             int M, int Nc, int K) {
    __shared__ float As[16][64];
    __shared__ float Bs[16][64];
    const int tid = threadIdx.x;
    const int tx = tid & 15;
    const int ty = tid >> 4;
    const int row0 = blockIdx.y * 64;
    const int col0 = blockIdx.x * 64;

    float acc[4][4] = {};

    for (int k0 = 0; k0 < K; k0 += 16) {
        #pragma unroll
        for (int i = tid; i < 64 * 16; i += 256) {
            int r = i >> 4, c = i & 15;
            int gr = row0 + r;
            As[c][r] = (gr < M) ? A[(size_t)gr * K + k0 + c] : 0.0f;
        }
        #pragma unroll
        for (int i = tid; i < 16 * 64; i += 256) {
            int r = i >> 6, c = i & 63;
            Bs[r][c] = B[(size_t)(k0 + r) * Nc + col0 + c];
        }
        __syncthreads();
        #pragma unroll
        for (int k = 0; k < 16; k++) {
            float a[4], b[4];
            #pragma unroll
            for (int i = 0; i < 4; i++) a[i] = As[k][ty * 4 + i];
            #pragma unroll
            for (int j = 0; j < 4; j++) b[j] = Bs[k][tx * 4 + j];
            #pragma unroll
            for (int i = 0; i < 4; i++)
                #pragma unroll
                for (int j = 0; j < 4; j++)
                    acc[i][j] += a[i] * b[j];
        }
        __syncthreads();
    }

    #pragma unroll
    for (int i = 0; i < 4; i++) {
        int gr = row0 + ty * 4 + i;
        if (gr >= M) continue;
        #pragma unroll
        for (int j = 0; j < 4; j++)
            C[(size_t)gr * Nc + col0 + tx * 4 + j] = acc[i][j];
    }
}

// ---------------------------------------------------------------------------
// Per-node attention coefficients + self-loop max init.
// ---------------------------------------------------------------------------
__global__ void alphas_kernel(const float* __restrict__ H,
                              const float* __restrict__ a_src,
                              const float* __restrict__ a_dst,
                              float* __restrict__ AS, float* __restrict__ AD,
                              float* __restrict__ MX,
                              int n, int heads, int D) {
    int i = blockIdx.x * blockDim.x + threadIdx.x;
    if (i >= n * heads) return;
    int node = i / heads, h = i % heads;
    const float* hr = H + (size_t)node * heads * D + h * D;
    float s = 0.0f, d = 0.0f;
    for (int k = 0; k < D; k++) {
        float v = hr[k];
        s += v * a_src[h * D + k];
        d += v * a_dst[h * D + k];
    }
    AS[i] = s;
    AD[i] = d;
    MX[i] = leaky(s + d);  // self-loop initializes running max
}

__global__ void edge_max_kernel(const int* __restrict__ ei,
                                const float* __restrict__ AS,
                                const float* __restrict__ AD,
                                float* __restrict__ MX,
                                int E, int heads) {
    int i = blockIdx.x * blockDim.x + threadIdx.x;
    if (i >= E * heads) return;
    int e = i / heads, h = i % heads;
    int s = ei[e];
    int d = ei[E + e];
    float v = leaky(AS[s * heads + h] + AD[d * heads + h]);
    atomicMaxF(&MX[d * heads + h], v);
}

__global__ void denom_init_kernel(const float* __restrict__ AS,
                                  const float* __restrict__ AD,
                                  const float* __restrict__ MX,
                                  float* __restrict__ DEN,
                                  int n, int heads) {
    int i = blockIdx.x * blockDim.x + threadIdx.x;
    if (i >= n * heads) return;
    float self_e = leaky(AS[i] + AD[i]);
    DEN[i] = __expf(self_e - MX[i]);
}

__global__ void edge_denom_kernel(const int* __restrict__ ei,
                                  const float* __restrict__ AS,
                                  const float* __restrict__ AD,
                                  const float* __restrict__ MX,
                                  float* __restrict__ DEN,
                                  int E, int heads) {
    int i = blockIdx.x * blockDim.x + threadIdx.x;
    if (i >= E * heads) return;
    int e = i / heads, h = i % heads;
    int s = ei[e];
    int d = ei[E + e];
    float v = leaky(AS[s * heads + h] + AD[d * heads + h]);
    atomicAdd(&DEN[d * heads + h], __expf(v - MX[d * heads + h]));
}

// out[n, h*D+k] = H[n, h*D+k] * softmax-weight(self loop)
__global__ void out_init_kernel(const float* __restrict__ H,
                                const float* __restrict__ AS,
                                const float* __restrict__ AD,
                                const float* __restrict__ MX,
                                const float* __restrict__ DEN,
                                float* __restrict__ OUT,
                                int n, int heads, int D) {
    int i = blockIdx.x * blockDim.x + threadIdx.x;
    int HD = heads * D;
    if (i >= n * HD) return;
    int node = i / HD;
    int h = (i % HD) / D;
    int a = node * heads + h;
    float self_e = leaky(AS[a] + AD[a]);
    float w = __expf(self_e - MX[a]) / (DEN[a] + 1e-16f);
    OUT[i] = H[i] * w;
}

// warp per edge: accumulate weighted source features into destination rows
__global__ void edge_agg_kernel(const int* __restrict__ ei,
                                const float* __restrict__ AS,
                                const float* __restrict__ AD,
                                const float* __restrict__ MX,
                                const float* __restrict__ DEN,
                                const float* __restrict__ H,
                                float* __restrict__ OUT,
                                int E, int heads, int D) {
    int warp = (blockIdx.x * blockDim.x + threadIdx.x) >> 5;
    int lane = threadIdx.x & 31;
    if (warp >= E) return;
    int s = ei[warp];
    int d = ei[E + warp];
    int HD = heads * D;
    for (int h = 0; h < heads; h++) {
        float v = leaky(AS[s * heads + h] + AD[d * heads + h]);
        float w = __expf(v - MX[d * heads + h]) / (DEN[d * heads + h] + 1e-16f);
        const float* hs = H + (size_t)s * HD + h * D;
        float* od = OUT + (size_t)d * HD + h * D;
        for (int k = lane; k < D; k += 32)
            atomicAdd(&od[k], __ldg(&hs[k]) * w);
    }
}

__global__ void bias_elu_kernel(float* __restrict__ OUT,
                                const float* __restrict__ bias,
                                int n, int HD) {
    int i = blockIdx.x * blockDim.x + threadIdx.x;
    if (i >= n * HD) return;
    float v = OUT[i] + bias[i % HD];
    OUT[i] = v > 0.0f ? v : (__expf(v) - 1.0f);
}

__global__ void pool_zero_kernel(float* __restrict__ POOL, float* __restrict__ CNT) {
    int i = blockIdx.x * blockDim.x + threadIdx.x;
    if (i < 2 * GNUM * 64) POOL[i] = 0.0f;
    if (i < 2 * GNUM) CNT[i] = 0.0f;
}

__global__ void pool_add_kernel(const float* __restrict__ OUT2,
                                const int* __restrict__ batch,
                                float* __restrict__ POOL, float* __restrict__ CNT,
                                int n) {
    int i = blockIdx.x * blockDim.x + threadIdx.x;
    if (i >= n * 64) return;
    int node = i >> 6;
    int d = i & 63;
    int g = batch[node];
    atomicAdd(&POOL[g * 64 + d], OUT2[i]);
    if (d == 0) atomicAdd(&CNT[g], 1.0f);
}

__global__ void final_write_kernel(const float* __restrict__ POOL,
                                   const float* __restrict__ CNT,
                                   float* __restrict__ out) {
    int i = blockIdx.x * blockDim.x + threadIdx.x;
    if (i >= 2 * GNUM * 64) return;
    float c = CNT[i >> 6];
    out[i] = POOL[i] / fmaxf(c, 1.0f);
}

// ---------------------------------------------------------------------------
// Launch
// ---------------------------------------------------------------------------
extern "C" void kernel_launch(void* const* d_in, const int* in_sizes, int n_in,
                              void* d_out, int out_size) {
    const float* x1  = (const float*)d_in[0];
    const int*   ei1 = (const int*)d_in[1];
    const int*   bt1 = (const int*)d_in[2];
    const float* x2  = (const float*)d_in[3];
    const int*   ei2 = (const int*)d_in[4];
    const int*   bt2 = (const int*)d_in[5];
    const float* W1  = (const float*)d_in[6];
    const float* as1 = (const float*)d_in[7];
    const float* ad1 = (const float*)d_in[8];
    const float* b1  = (const float*)d_in[9];
    const float* W2  = (const float*)d_in[10];
    const float* as2 = (const float*)d_in[11];
    const float* ad2 = (const float*)d_in[12];
    const float* b2  = (const float*)d_in[13];

    const int n = in_sizes[0] / 128;
    const int e = in_sizes[1] / 2;

    float *H, *OUT, *H2, *OUT2, *AS, *AD, *MX, *DEN, *POOL, *CNT;
    cudaGetSymbolAddress((void**)&H,    g_H);
    cudaGetSymbolAddress((void**)&OUT,  g_OUT);
    cudaGetSymbolAddress((void**)&H2,   g_H2);
    cudaGetSymbolAddress((void**)&OUT2, g_OUT2);
    cudaGetSymbolAddress((void**)&AS,   g_AS);
    cudaGetSymbolAddress((void**)&AD,   g_AD);
    cudaGetSymbolAddress((void**)&MX,   g_MAX);
    cudaGetSymbolAddress((void**)&DEN,  g_DEN);
    cudaGetSymbolAddress((void**)&POOL, g_POOL);
    cudaGetSymbolAddress((void**)&CNT,  g_CNT);

    pool_zero_kernel<<<cdiv(2 * GNUM * 64, 256), 256>>>(POOL, CNT);

    for (int g = 0; g < 2; g++) {
        const float* x  = g ? x2  : x1;
        const int*   ei = g ? ei2 : ei1;
        const int*   bt = g ? bt2 : bt1;

        // ---- conv1: GAT(128 -> 64, heads=4, concat) ----
        {
            dim3 grid(256 / 64, cdiv(n, 64));
            sgemm_kernel<<<grid, 256>>>(x, W1, H, n, 256, 128);
        }
        alphas_kernel<<<cdiv(n * 4, 256), 256>>>(H, as1, ad1, AS, AD, MX, n, 4, 64);
        edge_max_kernel<<<cdiv(e * 4, 256), 256>>>(ei, AS, AD, MX, e, 4);
        denom_init_kernel<<<cdiv(n * 4, 256), 256>>>(AS, AD, MX, DEN, n, 4);
        edge_denom_kernel<<<cdiv(e * 4, 256), 256>>>(ei, AS, AD, MX, DEN, e, 4);
        out_init_kernel<<<cdiv(n * 256, 256), 256>>>(H, AS, AD, MX, DEN, OUT, n, 4, 64);
        edge_agg_kernel<<<cdiv(e, 8), 256>>>(ei, AS, AD, MX, DEN, H, OUT, e, 4, 64);
        bias_elu_kernel<<<cdiv(n * 256, 256), 256>>>(OUT, b1, n, 256);

        // ---- conv2: GAT(256 -> 64, heads=1) ----
        {
            dim3 grid(64 / 64, cdiv(n, 64));
            sgemm_kernel<<<grid, 256>>>(OUT, W2, H2, n, 64, 256);
        }
        alphas_kernel<<<cdiv(n, 256), 256>>>(H2, as2, ad2, AS, AD, MX, n, 1, 64);
        edge_max_kernel<<<cdiv(e, 256), 256>>>(ei, AS, AD, MX, e, 1);
        denom_init_kernel<<<cdiv(n, 256), 256>>>(AS, AD, MX, DEN, n, 1);
        edge_denom_kernel<<<cdiv(e, 256), 256>>>(ei, AS, AD, MX, DEN, e, 1);
        out_init_kernel<<<cdiv(n * 64, 256), 256>>>(H2, AS, AD, MX, DEN, OUT2, n, 1, 64);
        edge_agg_kernel<<<cdiv(e, 8), 256>>>(ei, AS, AD, MX, DEN, H2, OUT2, e, 1, 64);
        bias_elu_kernel<<<cdiv(n * 64, 256), 256>>>(OUT2, b2, n, 64);

        // ---- mean pool ----
        pool_add_kernel<<<cdiv(n * 64, 256), 256>>>(OUT2, bt,
                                                    POOL + g * GNUM * 64,
                                                    CNT + g * GNUM, n);
    }

    final_write_kernel<<<cdiv(2 * GNUM * 64, 256), 256>>>(POOL, CNT, (float*)d_out);
}

// round 3
// speedup vs baseline: 2.6897x; 2.6897x over previous
#include <cuda_runtime.h>
#include <cstdint>

// ---------------------------------------------------------------------------
// GATGraphSimilarity: Siamese 2-layer GAT (heads=4 then 1) + mean pool.
// Round 2: CSR gather (no feature atomics), fused softmax+aggregate+ELU,
// 128x64 SGEMM with fused alpha epilogue, conv2 fused into pooling.
// ---------------------------------------------------------------------------

#define NMAX 50000
#define EMAX 800000
#define GNUM 64
#define NEG_SLOPE 0.2f

__device__ float g_H   [(size_t)NMAX * 256];  // conv1 pre-agg features
__device__ float g_OUT [(size_t)NMAX * 256];  // conv1 output (elu'd)
__device__ float g_H2  [(size_t)NMAX * 64];   // conv2 pre-agg features
__device__ float g_AS  [NMAX * 4];
__device__ float g_AD  [NMAX * 4];
__device__ int   g_DEG [NMAX];
__device__ int   g_ROWPTR[NMAX + 1];
__device__ int   g_CUR [NMAX];
__device__ int   g_ECOL[EMAX];
__device__ float g_POOL[2 * GNUM * 64];
__device__ float g_CNT [2 * GNUM];

static inline int cdiv(int a, int b) { return (a + b - 1) / b; }

__device__ __forceinline__ float leaky(float v) {
    return v > 0.0f ? v : NEG_SLOPE * v;
}

// ---------------------------------------------------------------------------
// CSR build
// ---------------------------------------------------------------------------
__global__ void deg_zero_kernel(int* __restrict__ deg, int n) {
    int i = blockIdx.x * blockDim.x + threadIdx.x;
    if (i < n) deg[i] = 0;
}

__global__ void hist_kernel(const int* __restrict__ ei, int* __restrict__ deg, int E) {
    int i = blockIdx.x * blockDim.x + threadIdx.x;
    if (i < E) atomicAdd(&deg[ei[E + i]], 1);
}

// single-block exclusive scan over deg[0..n) -> rowptr, cursor
__global__ void scan_kernel(const int* __restrict__ deg,
                            int* __restrict__ rowptr, int* __restrict__ cur, int n) {
    __shared__ int part[1024];
    int t = threadIdx.x;
    int chunk = (n + 1023) / 1024;
    int start = t * chunk;
    int end = start + chunk; if (end > n) end = n;
    int s = 0;
    for (int i = start; i < end; i++) s += deg[i];
    part[t] = s;
    __syncthreads();
    // inclusive Hillis-Steele
    for (int off = 1; off < 1024; off <<= 1) {
        int v = (t >= off) ? part[t - off] : 0;
        __syncthreads();
        part[t] += v;
        __syncthreads();
    }
    int base = (t == 0) ? 0 : part[t - 1];
    for (int i = start; i < end; i++) {
        rowptr[i] = base;
        cur[i] = base;
        base += deg[i];
    }
    if (end == n && start < n) rowptr[n] = base;
    if (n <= start && t == 0) rowptr[n] = part[1023]; // safety (unused for n>=1024)
}

__global__ void fill_kernel(const int* __restrict__ ei,
                            const int* __restrict__ rowptr_unused,
                            int* __restrict__ cur, int* __restrict__ ecol, int E) {
    int i = blockIdx.x * blockDim.x + threadIdx.x;
    if (i >= E) return;
    int s = ei[i];
    int d = ei[E + i];
    int slot = atomicAdd(&cur[d], 1);
    ecol[slot] = s;
}

// ---------------------------------------------------------------------------
// SGEMM 128x64 tile, 256 threads (16x16), 8x4 micro-tile, fused alpha epilogue.
// C[M,Nc] = A[M,K] @ B[K,Nc].  Each 64-col block = one head.
// AS[m,h] = dot(C row head-slice, a_src[h]);  AD likewise.
// ---------------------------------------------------------------------------
__global__ void sgemm_alpha_kernel(const float* __restrict__ A,
                                   const float* __restrict__ B,
                                   float* __restrict__ C,
                                   const float* __restrict__ a_src,
                                   const float* __restrict__ a_dst,
                                   float* __restrict__ AS,
                                   float* __restrict__ AD,
                                   int M, int Nc, int K, int heads) {
    __shared__ float As[16][128];
    __shared__ float Bs[16][64];
    const int tid = threadIdx.x;
    const int tx = tid & 15;
    const int ty = tid >> 4;
    const int row0 = blockIdx.y * 128;
    const int col0 = blockIdx.x * 64;
    const int h = col0 >> 6;

    float acc[8][4] = {};

    for (int k0 = 0; k0 < K; k0 += 16) {
        // A tile: 128 rows x 16 k, 512 float4 slots, 2 per thread
        #pragma unroll
        for (int q = 0; q < 2; q++) {
            int s4 = tid * 2 + q;
            int r = s4 >> 2;
            int c = (s4 & 3) * 4;
            int gr = row0 + r;
            float4 v = make_float4(0.f, 0.f, 0.f, 0.f);
            if (gr < M) v = *(const float4*)&A[(size_t)gr * K + k0 + c];
            As[c + 0][r] = v.x; As[c + 1][r] = v.y;
            As[c + 2][r] = v.z; As[c + 3][r] = v.w;
        }
        // B tile: 16 rows x 64 cols, 1 float4 per thread
        {
            int r = tid >> 4;
            int c = (tid & 15) * 4;
            *(float4*)&Bs[r][c] = *(const float4*)&B[(size_t)(k0 + r) * Nc + col0 + c];
        }
        __syncthreads();
        #pragma unroll
        for (int k = 0; k < 16; k++) {
            float4 b4 = *(const float4*)&Bs[k][tx * 4];
            float4 a0 = *(const float4*)&As[k][ty * 8];
            float4 a1 = *(const float4*)&As[k][ty * 8 + 4];
            float a[8] = {a0.x, a0.y, a0.z, a0.w, a1.x, a1.y, a1.z, a1.w};
            float b[4] = {b4.x, b4.y, b4.z, b4.w};
            #pragma unroll
            for (int i = 0; i < 8; i++)
                #pragma unroll
                for (int j = 0; j < 4; j++)
                    acc[i][j] += a[i] * b[j];
        }
        __syncthreads();
    }

    // store C
    #pragma unroll
    for (int i = 0; i < 8; i++) {
        int gr = row0 + ty * 8 + i;
        if (gr >= M) continue;
        float4 v = make_float4(acc[i][0], acc[i][1], acc[i][2], acc[i][3]);
        *(float4*)&C[(size_t)gr * Nc + col0 + tx * 4] = v;
    }

    // alpha epilogue: per-row dot with a_src/a_dst over this 64-col head block
    float4 asv = *(const float4*)&a_src[h * 64 + tx * 4];
    float4 adv = *(const float4*)&a_dst[h * 64 + tx * 4];
    #pragma unroll
    for (int i = 0; i < 8; i++) {
        float s = acc[i][0] * asv.x + acc[i][1] * asv.y + acc[i][2] * asv.z + acc[i][3] * asv.w;
        float d = acc[i][0] * adv.x + acc[i][1] * adv.y + acc[i][2] * adv.z + acc[i][3] * adv.w;
        #pragma unroll
        for (int off = 8; off >= 1; off >>= 1) {
            s += __shfl_down_sync(0xffffffffu, s, off, 16);
            d += __shfl_down_sync(0xffffffffu, d, off, 16);
        }
        if (tx == 0) {
            int gr = row0 + ty * 8 + i;
            if (gr < M) {
                AS[gr * heads + h] = s;
                AD[gr * heads + h] = d;
            }
        }
    }
}

// ---------------------------------------------------------------------------
// Fused GAT aggregation: warp per destination node.
// Pass 1 (lane-strided): running max of leaky(as[src]+ad[dst]) incl. self loop.
// Pass 2 (warp-sequential over edges): softmax weights + feature accumulate.
// Epilogue: normalize, +bias, ELU. HEADS==1 path pools instead of writing OUT.
// ---------------------------------------------------------------------------
template <int HEADS, bool POOLING>
__global__ void gat_agg_kernel(const int* __restrict__ rowptr,
                               const int* __restrict__ ecol,
                               const float* __restrict__ AS,
                               const float* __restrict__ AD,
                               const float* __restrict__ H,
                               const float* __restrict__ bias,
                               float* __restrict__ OUT,
                               const int* __restrict__ batch,
                               float* __restrict__ POOL,
                               float* __restrict__ CNT,
                               int n) {
    const int warp = (blockIdx.x * blockDim.x + threadIdx.x) >> 5;
    const int lane = threadIdx.x & 31;
    if (warp >= n) return;
    const int d = warp;
    const int beg = rowptr[d];
    const int end = rowptr[d + 1];
    const int HD = HEADS * 64;

    float ad_d[HEADS], self_e[HEADS], mx[HEADS];
    #pragma unroll
    for (int h = 0; h < HEADS; h++) {
        ad_d[h] = AD[d * HEADS + h];
        self_e[h] = leaky(AS[d * HEADS + h] + ad_d[h]);
        mx[h] = self_e[h];
    }

    // pass 1: max (lane-strided over edges)
    for (int j = beg + lane; j < end; j += 32) {
        int s = ecol[j];
        if (HEADS == 4) {
            float4 a4 = *(const float4*)&AS[s * 4];
            mx[0] = fmaxf(mx[0], leaky(a4.x + ad_d[0]));
            mx[1] = fmaxf(mx[1], leaky(a4.y + ad_d[1]));
            mx[2] = fmaxf(mx[2], leaky(a4.z + ad_d[2]));
            mx[3] = fmaxf(mx[3], leaky(a4.w + ad_d[3]));
        } else {
            mx[0] = fmaxf(mx[0], leaky(AS[s] + ad_d[0]));
        }
    }
    #pragma unroll
    for (int h = 0; h < HEADS; h++) {
        #pragma unroll
        for (int off = 16; off >= 1; off >>= 1)
            mx[h] = fmaxf(mx[h], __shfl_xor_sync(0xffffffffu, mx[h], off));
    }

    // pass 2: denom + weighted accumulate (each lane owns 2 dims per head)
    float den[HEADS];
    float acc[HEADS][2];
    #pragma unroll
    for (int h = 0; h < HEADS; h++) {
        float ex = __expf(self_e[h] - mx[h]);
        den[h] = ex;
        float2 hv = *(const float2*)&H[(size_t)d * HD + h * 64 + lane * 2];
        acc[h][0] = ex * hv.x;
        acc[h][1] = ex * hv.y;
    }
    for (int j = beg; j < end; j++) {
        int s = ecol[j];  // broadcast
        if (HEADS == 4) {
            float4 a4 = *(const float4*)&AS[s * 4];
            float e0 = __expf(leaky(a4.x + ad_d[0]) - mx[0]);
            float e1 = __expf(leaky(a4.y + ad_d[1]) - mx[1]);
            float e2 = __expf(leaky(a4.z + ad_d[2]) - mx[2]);
            float e3 = __expf(leaky(a4.w + ad_d[3]) - mx[3]);
            den[0] += e0; den[1] += e1; den[2] += e2; den[3] += e3;
            const float* hr = &H[(size_t)s * 256 + lane * 2];
            float2 h0 = *(const float2*)&hr[0];
            float2 h1 = *(const float2*)&hr[64];
            float2 h2 = *(const float2*)&hr[128];
            float2 h3 = *(const float2*)&hr[192];
            acc[0][0] += e0 * h0.x; acc[0][1] += e0 * h0.y;
            acc[1][0] += e1 * h1.x; acc[1][1] += e1 * h1.y;
            acc[2][0] += e2 * h2.x; acc[2][1] += e2 * h2.y;
            acc[3][0] += e3 * h3.x; acc[3][1] += e3 * h3.y;
        } else {
            float ex = __expf(leaky(AS[s] + ad_d[0]) - mx[0]);
            den[0] += ex;
            float2 hv = *(const float2*)&H[(size_t)s * 64 + lane * 2];
            acc[0][0] += ex * hv.x;
            acc[0][1] += ex * hv.y;
        }
    }

    // epilogue: normalize + bias + ELU
    #pragma unroll
    for (int h = 0; h < HEADS; h++) {
        float inv = 1.0f / (den[h] + 1e-16f);
        float v0 = acc[h][0] * inv + bias[h * 64 + lane * 2 + 0];
        float v1 = acc[h][1] * inv + bias[h * 64 + lane * 2 + 1];
        v0 = v0 > 0.0f ? v0 : (__expf(v0) - 1.0f);
        v1 = v1 > 0.0f ? v1 : (__expf(v1) - 1.0f);
        if (POOLING) {
            int g = batch[d];
            atomicAdd(&POOL[g * 64 + lane * 2 + 0], v0);
            atomicAdd(&POOL[g * 64 + lane * 2 + 1], v1);
            if (lane == 0 && h == 0) atomicAdd(&CNT[g], 1.0f);
        } else {
            float2 ov = make_float2(v0, v1);
            *(float2*)&OUT[(size_t)d * HD + h * 64 + lane * 2] = ov;
        }
    }
}

__global__ void pool_zero_kernel(float* __restrict__ POOL, float* __restrict__ CNT) {
    int i = blockIdx.x * blockDim.x + threadIdx.x;
    if (i < 2 * GNUM * 64) POOL[i] = 0.0f;
    if (i < 2 * GNUM) CNT[i] = 0.0f;
}

__global__ void final_write_kernel(const float* __restrict__ POOL,
                                   const float* __restrict__ CNT,
                                   float* __restrict__ out) {
    int i = blockIdx.x * blockDim.x + threadIdx.x;
    if (i >= 2 * GNUM * 64) return;
    float c = CNT[i >> 6];
    out[i] = POOL[i] / fmaxf(c, 1.0f);
}

// ---------------------------------------------------------------------------
// Launch
// ---------------------------------------------------------------------------
extern "C" void kernel_launch(void* const* d_in, const int* in_sizes, int n_in,
                              void* d_out, int out_size) {
    const float* x1  = (const float*)d_in[0];
    const int*   ei1 = (const int*)d_in[1];
    const int*   bt1 = (const int*)d_in[2];
    const float* x2  = (const float*)d_in[3];
    const int*   ei2 = (const int*)d_in[4];
    const int*   bt2 = (const int*)d_in[5];
    const float* W1  = (const float*)d_in[6];
    const float* as1 = (const float*)d_in[7];
    const float* ad1 = (const float*)d_in[8];
    const float* b1  = (const float*)d_in[9];
    const float* W2  = (const float*)d_in[10];
    const float* as2 = (const float*)d_in[11];
    const float* ad2 = (const float*)d_in[12];
    const float* b2  = (const float*)d_in[13];

    const int n = in_sizes[0] / 128;
    const int e = in_sizes[1] / 2;

    float *H, *OUT, *H2, *AS, *AD, *POOL, *CNT;
    int *DEG, *ROWPTR, *CUR, *ECOL;
    cudaGetSymbolAddress((void**)&H,      g_H);
    cudaGetSymbolAddress((void**)&OUT,    g_OUT);
    cudaGetSymbolAddress((void**)&H2,     g_H2);
    cudaGetSymbolAddress((void**)&AS,     g_AS);
    cudaGetSymbolAddress((void**)&AD,     g_AD);
    cudaGetSymbolAddress((void**)&DEG,    g_DEG);
    cudaGetSymbolAddress((void**)&ROWPTR, g_ROWPTR);
    cudaGetSymbolAddress((void**)&CUR,    g_CUR);
    cudaGetSymbolAddress((void**)&ECOL,   g_ECOL);
    cudaGetSymbolAddress((void**)&POOL,   g_POOL);
    cudaGetSymbolAddress((void**)&CNT,    g_CNT);

    pool_zero_kernel<<<cdiv(2 * GNUM * 64, 256), 256>>>(POOL, CNT);

    for (int g = 0; g < 2; g++) {
        const float* x  = g ? x2  : x1;
        const int*   ei = g ? ei2 : ei1;
        const int*   bt = g ? bt2 : bt1;

        // CSR build (dst-sorted)
        deg_zero_kernel<<<cdiv(n, 256), 256>>>(DEG, n);
        hist_kernel<<<cdiv(e, 256), 256>>>(ei, DEG, e);
        scan_kernel<<<1, 1024>>>(DEG, ROWPTR, CUR, n);
        fill_kernel<<<cdiv(e, 256), 256>>>(ei, ROWPTR, CUR, ECOL, e);

        // conv1: GAT(128 -> 64, heads=4) : GEMM + alphas, then fused aggregate
        {
            dim3 grid(4, cdiv(n, 128));
            sgemm_alpha_kernel<<<grid, 256>>>(x, W1, H, as1, ad1, AS, AD, n, 256, 128, 4);
        }
        gat_agg_kernel<4, false><<<cdiv(n, 8), 256>>>(
            ROWPTR, ECOL, AS, AD, H, b1, OUT, nullptr, nullptr, nullptr, n);

        // conv2: GAT(256 -> 64, heads=1) : GEMM + alphas, fused aggregate + pool
        {
            dim3 grid(1, cdiv(n, 128));
            sgemm_alpha_kernel<<<grid, 256>>>(OUT, W2, H2, as2, ad2, AS, AD, n, 64, 256, 1);
        }
        gat_agg_kernel<1, true><<<cdiv(n, 8), 256>>>(
            ROWPTR, ECOL, AS, AD, H2, b2, nullptr, bt,
            POOL + g * GNUM * 64, CNT + g * GNUM, n);
    }

    final_write_kernel<<<cdiv(2 * GNUM * 64, 256), 256>>>(POOL, CNT, (float*)d_out);
}

// round 4
// speedup vs baseline: 2.8790x; 1.0704x over previous
#include <cuda_runtime.h>
#include <cstdint>

// ---------------------------------------------------------------------------
// GATGraphSimilarity: Siamese 2-layer GAT (heads=4 then 1) + mean pool.
// Round 3: multi-block scan (was 71us single-block), 8x8 GEMM microtile.
// ---------------------------------------------------------------------------

#define NMAX 50000
#define EMAX 800000
#define GNUM 64
#define NEG_SLOPE 0.2f
#define SCAN_CHUNK 4096   // elements per scan block (256 threads x 16)
#define SCAN_NB ((NMAX + SCAN_CHUNK - 1) / SCAN_CHUNK)

__device__ float g_H   [(size_t)NMAX * 256];
__device__ float g_OUT [(size_t)NMAX * 256];
__device__ float g_H2  [(size_t)NMAX * 64];
__device__ float g_AS  [NMAX * 4];
__device__ float g_AD  [NMAX * 4];
__device__ int   g_DEG [NMAX];
__device__ int   g_ROWPTR[NMAX + 1];
__device__ int   g_CUR [NMAX];
__device__ int   g_ECOL[EMAX];
__device__ int   g_PART[SCAN_NB + 1];
__device__ float g_POOL[2 * GNUM * 64];
__device__ float g_CNT [2 * GNUM];

static inline int cdiv(int a, int b) { return (a + b - 1) / b; }

__device__ __forceinline__ float leaky(float v) {
    return v > 0.0f ? v : NEG_SLOPE * v;
}

// ---------------------------------------------------------------------------
// CSR build
// ---------------------------------------------------------------------------
__global__ void deg_zero_kernel(int* __restrict__ deg, int n) {
    int i = blockIdx.x * blockDim.x + threadIdx.x;
    if (i < n) deg[i] = 0;
}

__global__ void hist_kernel(const int* __restrict__ ei, int* __restrict__ deg, int E) {
    int i = blockIdx.x * blockDim.x + threadIdx.x;
    if (i < E) atomicAdd(&deg[ei[E + i]], 1);
}

// scan stage 1: per-block sum of a contiguous 4096-elem chunk
__global__ void scan_partial_kernel(const int* __restrict__ deg,
                                    int* __restrict__ part, int n) {
    __shared__ int red[256];
    const int t = threadIdx.x;
    const int base = blockIdx.x * SCAN_CHUNK + t * 16;
    int s = 0;
    #pragma unroll
    for (int q = 0; q < 16; q++) {
        int i = base + q;
        if (i < n) s += deg[i];
    }
    red[t] = s;
    __syncthreads();
    #pragma unroll
    for (int off = 128; off >= 1; off >>= 1) {
        if (t < off) red[t] += red[t + off];
        __syncthreads();
    }
    if (t == 0) part[blockIdx.x] = red[0];
}

// scan stage 2: exclusive scan of block partials (tiny), total in part[nb]
__global__ void scan_root_kernel(int* __restrict__ part, int nb) {
    if (threadIdx.x == 0) {
        int run = 0;
        for (int i = 0; i < nb; i++) {
            int v = part[i];
            part[i] = run;
            run += v;
        }
        part[nb] = run;
    }
}

// scan stage 3: rescan chunk with block offset, write rowptr + cursor
__global__ void scan_final_kernel(const int* __restrict__ deg,
                                  const int* __restrict__ part,
                                  int* __restrict__ rowptr,
                                  int* __restrict__ cur,
                                  int n, int nb) {
    __shared__ int thr[256];
    const int t = threadIdx.x;
    const int base = blockIdx.x * SCAN_CHUNK + t * 16;
    int s = 0;
    int dloc[16];
    #pragma unroll
    for (int q = 0; q < 16; q++) {
        int i = base + q;
        dloc[q] = (i < n) ? deg[i] : 0;
        s += dloc[q];
    }
    thr[t] = s;
    __syncthreads();
    // inclusive Hillis-Steele over 256
    #pragma unroll
    for (int off = 1; off < 256; off <<= 1) {
        int v = (t >= off) ? thr[t - off] : 0;
        __syncthreads();
        thr[t] += v;
        __syncthreads();
    }
    int offset = part[blockIdx.x] + ((t == 0) ? 0 : thr[t - 1]);
    #pragma unroll
    for (int q = 0; q < 16; q++) {
        int i = base + q;
        if (i < n) {
            rowptr[i] = offset;
            cur[i] = offset;
            offset += dloc[q];
        }
    }
    if (blockIdx.x == 0 && t == 0) rowptr[n] = part[nb];
}

__global__ void fill_kernel(const int* __restrict__ ei,
                            int* __restrict__ cur, int* __restrict__ ecol, int E) {
    int i = blockIdx.x * blockDim.x + threadIdx.x;
    if (i >= E) return;
    int s = ei[i];
    int d = ei[E + i];
    int slot = atomicAdd(&cur[d], 1);
    ecol[slot] = s;
}

// ---------------------------------------------------------------------------
// SGEMM 128x64 tile, 128 threads (16x8), 8x8 micro-tile, fused alpha epilogue.
// C[M,Nc] = A[M,K] @ B[K,Nc]. Each 64-col block = one head.
// ---------------------------------------------------------------------------
__global__ void sgemm_alpha_kernel(const float* __restrict__ A,
                                   const float* __restrict__ B,
                                   float* __restrict__ C,
                                   const float* __restrict__ a_src,
                                   const float* __restrict__ a_dst,
                                   float* __restrict__ AS,
                                   float* __restrict__ AD,
                                   int M, int Nc, int K, int heads) {
    __shared__ float Asm[16][128];
    __shared__ float Bsm[16][64];
    const int tid = threadIdx.x;          // 128 threads
    const int tx = tid & 7;               // 8 col-groups
    const int ty = tid >> 3;              // 16 row-groups
    const int row0 = blockIdx.y * 128;
    const int col0 = blockIdx.x * 64;
    const int h = col0 >> 6;

    float acc[8][8] = {};

    for (int k0 = 0; k0 < K; k0 += 16) {
        // A tile: 128 rows x 16 k = 512 float4, 4 per thread
        #pragma unroll
        for (int q = 0; q < 4; q++) {
            int s4 = tid + q * 128;
            int r = s4 >> 2;
            int c = (s4 & 3) * 4;
            int gr = row0 + r;
            float4 v = make_float4(0.f, 0.f, 0.f, 0.f);
            if (gr < M) v = *(const float4*)&A[(size_t)gr * K + k0 + c];
            Asm[c + 0][r] = v.x; Asm[c + 1][r] = v.y;
            Asm[c + 2][r] = v.z; Asm[c + 3][r] = v.w;
        }
        // B tile: 16 rows x 64 cols = 256 float4, 2 per thread
        #pragma unroll
        for (int q = 0; q < 2; q++) {
            int s4 = tid + q * 128;
            int r = s4 >> 4;
            int c = (s4 & 15) * 4;
            *(float4*)&Bsm[r][c] = *(const float4*)&B[(size_t)(k0 + r) * Nc + col0 + c];
        }
        __syncthreads();
        #pragma unroll
        for (int k = 0; k < 16; k++) {
            float4 a0 = *(const float4*)&Asm[k][ty * 8];
            float4 a1 = *(const float4*)&Asm[k][ty * 8 + 4];
            float4 b0 = *(const float4*)&Bsm[k][tx * 8];
            float4 b1 = *(const float4*)&Bsm[k][tx * 8 + 4];
            float a[8] = {a0.x, a0.y, a0.z, a0.w, a1.x, a1.y, a1.z, a1.w};
            float b[8] = {b0.x, b0.y, b0.z, b0.w, b1.x, b1.y, b1.z, b1.w};
            #pragma unroll
            for (int i = 0; i < 8; i++)
                #pragma unroll
                for (int j = 0; j < 8; j++)
                    acc[i][j] += a[i] * b[j];
        }
        __syncthreads();
    }

    // store C
    #pragma unroll
    for (int i = 0; i < 8; i++) {
        int gr = row0 + ty * 8 + i;
        if (gr >= M) continue;
        float4 v0 = make_float4(acc[i][0], acc[i][1], acc[i][2], acc[i][3]);
        float4 v1 = make_float4(acc[i][4], acc[i][5], acc[i][6], acc[i][7]);
        *(float4*)&C[(size_t)gr * Nc + col0 + tx * 8]     = v0;
        *(float4*)&C[(size_t)gr * Nc + col0 + tx * 8 + 4] = v1;
    }

    // alpha epilogue: per-row dot over this 64-col head block
    float4 as0 = *(const float4*)&a_src[h * 64 + tx * 8];
    float4 as1 = *(const float4*)&a_src[h * 64 + tx * 8 + 4];
    float4 ad0 = *(const float4*)&a_dst[h * 64 + tx * 8];
    float4 ad1 = *(const float4*)&a_dst[h * 64 + tx * 8 + 4];
    #pragma unroll
    for (int i = 0; i < 8; i++) {
        float s = acc[i][0] * as0.x + acc[i][1] * as0.y + acc[i][2] * as0.z + acc[i][3] * as0.w
                + acc[i][4] * as1.x + acc[i][5] * as1.y + acc[i][6] * as1.z + acc[i][7] * as1.w;
        float d = acc[i][0] * ad0.x + acc[i][1] * ad0.y + acc[i][2] * ad0.z + acc[i][3] * ad0.w
                + acc[i][4] * ad1.x + acc[i][5] * ad1.y + acc[i][6] * ad1.z + acc[i][7] * ad1.w;
        #pragma unroll
        for (int off = 4; off >= 1; off >>= 1) {
            s += __shfl_down_sync(0xffffffffu, s, off, 8);
            d += __shfl_down_sync(0xffffffffu, d, off, 8);
        }
        if (tx == 0) {
            int gr = row0 + ty * 8 + i;
            if (gr < M) {
                AS[gr * heads + h] = s;
                AD[gr * heads + h] = d;
            }
        }
    }
}

// ---------------------------------------------------------------------------
// Fused GAT aggregation: warp per destination node (unchanged from round 2).
// ---------------------------------------------------------------------------
template <int HEADS, bool POOLING>
__global__ void gat_agg_kernel(const int* __restrict__ rowptr,
                               const int* __restrict__ ecol,
                               const float* __restrict__ AS,
                               const float* __restrict__ AD,
                               const float* __restrict__ H,
                               const float* __restrict__ bias,
                               float* __restrict__ OUT,
                               const int* __restrict__ batch,
                               float* __restrict__ POOL,
                               float* __restrict__ CNT,
                               int n) {
    const int warp = (blockIdx.x * blockDim.x + threadIdx.x) >> 5;
    const int lane = threadIdx.x & 31;
    if (warp >= n) return;
    const int d = warp;
    const int beg = rowptr[d];
    const int end = rowptr[d + 1];
    const int HD = HEADS * 64;

    float ad_d[HEADS], self_e[HEADS], mx[HEADS];
    #pragma unroll
    for (int h = 0; h < HEADS; h++) {
        ad_d[h] = AD[d * HEADS + h];
        self_e[h] = leaky(AS[d * HEADS + h] + ad_d[h]);
        mx[h] = self_e[h];
    }

    for (int j = beg + lane; j < end; j += 32) {
        int s = ecol[j];
        if (HEADS == 4) {
            float4 a4 = *(const float4*)&AS[s * 4];
            mx[0] = fmaxf(mx[0], leaky(a4.x + ad_d[0]));
            mx[1] = fmaxf(mx[1], leaky(a4.y + ad_d[1]));
            mx[2] = fmaxf(mx[2], leaky(a4.z + ad_d[2]));
            mx[3] = fmaxf(mx[3], leaky(a4.w + ad_d[3]));
        } else {
            mx[0] = fmaxf(mx[0], leaky(AS[s] + ad_d[0]));
        }
    }
    #pragma unroll
    for (int h = 0; h < HEADS; h++) {
        #pragma unroll
        for (int off = 16; off >= 1; off >>= 1)
            mx[h] = fmaxf(mx[h], __shfl_xor_sync(0xffffffffu, mx[h], off));
    }

    float den[HEADS];
    float acc[HEADS][2];
    #pragma unroll
    for (int h = 0; h < HEADS; h++) {
        float ex = __expf(self_e[h] - mx[h]);
        den[h] = ex;
        float2 hv = *(const float2*)&H[(size_t)d * HD + h * 64 + lane * 2];
        acc[h][0] = ex * hv.x;
        acc[h][1] = ex * hv.y;
    }
    for (int j = beg; j < end; j++) {
        int s = ecol[j];
        if (HEADS == 4) {
            float4 a4 = *(const float4*)&AS[s * 4];
            float e0 = __expf(leaky(a4.x + ad_d[0]) - mx[0]);
            float e1 = __expf(leaky(a4.y + ad_d[1]) - mx[1]);
            float e2 = __expf(leaky(a4.z + ad_d[2]) - mx[2]);
            float e3 = __expf(leaky(a4.w + ad_d[3]) - mx[3]);
            den[0] += e0; den[1] += e1; den[2] += e2; den[3] += e3;
            const float* hr = &H[(size_t)s * 256 + lane * 2];
            float2 h0 = *(const float2*)&hr[0];
            float2 h1 = *(const float2*)&hr[64];
            float2 h2 = *(const float2*)&hr[128];
            float2 h3 = *(const float2*)&hr[192];
            acc[0][0] += e0 * h0.x; acc[0][1] += e0 * h0.y;
            acc[1][0] += e1 * h1.x; acc[1][1] += e1 * h1.y;
            acc[2][0] += e2 * h2.x; acc[2][1] += e2 * h2.y;
            acc[3][0] += e3 * h3.x; acc[3][1] += e3 * h3.y;
        } else {
            float ex = __expf(leaky(AS[s] + ad_d[0]) - mx[0]);
            den[0] += ex;
            float2 hv = *(const float2*)&H[(size_t)s * 64 + lane * 2];
            acc[0][0] += ex * hv.x;
            acc[0][1] += ex * hv.y;
        }
    }

    #pragma unroll
    for (int h = 0; h < HEADS; h++) {
        float inv = 1.0f / (den[h] + 1e-16f);
        float v0 = acc[h][0] * inv + bias[h * 64 + lane * 2 + 0];
        float v1 = acc[h][1] * inv + bias[h * 64 + lane * 2 + 1];
        v0 = v0 > 0.0f ? v0 : (__expf(v0) - 1.0f);
        v1 = v1 > 0.0f ? v1 : (__expf(v1) - 1.0f);
        if (POOLING) {
            int g = batch[d];
            atomicAdd(&POOL[g * 64 + lane * 2 + 0], v0);
            atomicAdd(&POOL[g * 64 + lane * 2 + 1], v1);
            if (lane == 0 && h == 0) atomicAdd(&CNT[g], 1.0f);
        } else {
            float2 ov = make_float2(v0, v1);
            *(float2*)&OUT[(size_t)d * HD + h * 64 + lane * 2] = ov;
        }
    }
}

__global__ void pool_zero_kernel(float* __restrict__ POOL, float* __restrict__ CNT) {
    int i = blockIdx.x * blockDim.x + threadIdx.x;
    if (i < 2 * GNUM * 64) POOL[i] = 0.0f;
    if (i < 2 * GNUM) CNT[i] = 0.0f;
}

__global__ void final_write_kernel(const float* __restrict__ POOL,
                                   const float* __restrict__ CNT,
                                   float* __restrict__ out) {
    int i = blockIdx.x * blockDim.x + threadIdx.x;
    if (i >= 2 * GNUM * 64) return;
    float c = CNT[i >> 6];
    out[i] = POOL[i] / fmaxf(c, 1.0f);
}

// ---------------------------------------------------------------------------
// Launch
// ---------------------------------------------------------------------------
extern "C" void kernel_launch(void* const* d_in, const int* in_sizes, int n_in,
                              void* d_out, int out_size) {
    const float* x1  = (const float*)d_in[0];
    const int*   ei1 = (const int*)d_in[1];
    const int*   bt1 = (const int*)d_in[2];
    const float* x2  = (const float*)d_in[3];
    const int*   ei2 = (const int*)d_in[4];
    const int*   bt2 = (const int*)d_in[5];
    const float* W1  = (const float*)d_in[6];
    const float* as1 = (const float*)d_in[7];
    const float* ad1 = (const float*)d_in[8];
    const float* b1  = (const float*)d_in[9];
    const float* W2  = (const float*)d_in[10];
    const float* as2 = (const float*)d_in[11];
    const float* ad2 = (const float*)d_in[12];
    const float* b2  = (const float*)d_in[13];

    const int n = in_sizes[0] / 128;
    const int e = in_sizes[1] / 2;
    const int nb = cdiv(n, SCAN_CHUNK);

    float *H, *OUT, *H2, *AS, *AD, *POOL, *CNT;
    int *DEG, *ROWPTR, *CUR, *ECOL, *PART;
    cudaGetSymbolAddress((void**)&H,      g_H);
    cudaGetSymbolAddress((void**)&OUT,    g_OUT);
    cudaGetSymbolAddress((void**)&H2,     g_H2);
    cudaGetSymbolAddress((void**)&AS,     g_AS);
    cudaGetSymbolAddress((void**)&AD,     g_AD);
    cudaGetSymbolAddress((void**)&DEG,    g_DEG);
    cudaGetSymbolAddress((void**)&ROWPTR, g_ROWPTR);
    cudaGetSymbolAddress((void**)&CUR,    g_CUR);
    cudaGetSymbolAddress((void**)&ECOL,   g_ECOL);
    cudaGetSymbolAddress((void**)&PART,   g_PART);
    cudaGetSymbolAddress((void**)&POOL,   g_POOL);
    cudaGetSymbolAddress((void**)&CNT,    g_CNT);

    pool_zero_kernel<<<cdiv(2 * GNUM * 64, 256), 256>>>(POOL, CNT);

    for (int g = 0; g < 2; g++) {
        const float* x  = g ? x2  : x1;
        const int*   ei = g ? ei2 : ei1;
        const int*   bt = g ? bt2 : bt1;

        // CSR build (dst-sorted)
        deg_zero_kernel<<<cdiv(n, 256), 256>>>(DEG, n);
        hist_kernel<<<cdiv(e, 256), 256>>>(ei, DEG, e);
        scan_partial_kernel<<<nb, 256>>>(DEG, PART, n);
        scan_root_kernel<<<1, 32>>>(PART, nb);
        scan_final_kernel<<<nb, 256>>>(DEG, PART, ROWPTR, CUR, n, nb);
        fill_kernel<<<cdiv(e, 256), 256>>>(ei, CUR, ECOL, e);

        // conv1: GAT(128 -> 64, heads=4)
        {
            dim3 grid(4, cdiv(n, 128));
            sgemm_alpha_kernel<<<grid, 128>>>(x, W1, H, as1, ad1, AS, AD, n, 256, 128, 4);
        }
        gat_agg_kernel<4, false><<<cdiv(n, 8), 256>>>(
            ROWPTR, ECOL, AS, AD, H, b1, OUT, nullptr, nullptr, nullptr, n);

        // conv2: GAT(256 -> 64, heads=1), fused pooling
        {
            dim3 grid(1, cdiv(n, 128));
            sgemm_alpha_kernel<<<grid, 128>>>(OUT, W2, H2, as2, ad2, AS, AD, n, 64, 256, 1);
        }
        gat_agg_kernel<1, true><<<cdiv(n, 8), 256>>>(
            ROWPTR, ECOL, AS, AD, H2, b2, nullptr, bt,
            POOL + g * GNUM * 64, CNT + g * GNUM, n);
    }

    final_write_kernel<<<cdiv(2 * GNUM * 64, 256), 256>>>(POOL, CNT, (float*)d_out);
}

// round 6
// speedup vs baseline: 3.6769x; 1.2772x over previous
#include <cuda_runtime.h>
#include <cuda_bf16.h>
#include <cstdint>

// ---------------------------------------------------------------------------
// GATGraphSimilarity: Siamese 2-layer GAT (heads=4 then 1) + mean pool.
// Round 6: GEMMs via mma.sync m16n8k16 bf16 (split hi/lo, fp32 accum) --
// tcgen05 is unavailable because the harness assembles for sm_103 (no 'a').
// Fused alpha epilogue. CSR build + fused aggregation unchanged.
// ---------------------------------------------------------------------------

#define NMAX 50000
#define EMAX 800000
#define GNUM 64
#define NEG_SLOPE 0.2f
#define SCAN_CHUNK 4096
#define SCAN_NB ((NMAX + SCAN_CHUNK - 1) / SCAN_CHUNK)

__device__ float g_H   [(size_t)NMAX * 256];
__device__ float g_OUT [(size_t)NMAX * 256];
__device__ float g_H2  [(size_t)NMAX * 64];
__device__ float g_AS  [NMAX * 4];
__device__ float g_AD  [NMAX * 4];
__device__ int   g_DEG [NMAX];
__device__ int   g_ROWPTR[NMAX + 1];
__device__ int   g_CUR [NMAX];
__device__ int   g_ECOL[EMAX];
__device__ int   g_PART[SCAN_NB + 1];
__device__ float g_POOL[2 * GNUM * 64];
__device__ float g_CNT [2 * GNUM];
// transposed split-bf16 weights: [N, K] row-major, K contiguous
__device__ __nv_bfloat16 g_W1T_HI[256 * 128];
__device__ __nv_bfloat16 g_W1T_LO[256 * 128];
__device__ __nv_bfloat16 g_W2T_HI[64 * 256];
__device__ __nv_bfloat16 g_W2T_LO[64 * 256];

static inline int cdiv(int a, int b) { return (a + b - 1) / b; }

__device__ __forceinline__ float leaky(float v) {
    return v > 0.0f ? v : NEG_SLOPE * v;
}

__device__ __forceinline__ uint32_t bf2u(__nv_bfloat162 v) {
    return *reinterpret_cast<uint32_t*>(&v);
}

// D += A * B  (m16n8k16, bf16 inputs, f32 accumulate)
__device__ __forceinline__ void mma16816(float* d, const uint32_t* a, const uint32_t* b) {
    asm volatile(
        "mma.sync.aligned.m16n8k16.row.col.f32.bf16.bf16.f32 "
        "{%0,%1,%2,%3}, {%4,%5,%6,%7}, {%8,%9}, {%0,%1,%2,%3};"
        : "+f"(d[0]), "+f"(d[1]), "+f"(d[2]), "+f"(d[3])
        : "r"(a[0]), "r"(a[1]), "r"(a[2]), "r"(a[3]), "r"(b[0]), "r"(b[1]));
}

// ---------------------------------------------------------------------------
// Weight prep: W[K,N] fp32 -> Wt_hi/Wt_lo [N,K] bf16 (split precision)
// ---------------------------------------------------------------------------
__global__ void prep_w_kernel(const float* __restrict__ W,
                              __nv_bfloat16* __restrict__ hi,
                              __nv_bfloat16* __restrict__ lo,
                              int K, int N) {
    int i = blockIdx.x * blockDim.x + threadIdx.x;
    if (i >= N * K) return;
    int n = i / K, k = i % K;
    float v = W[(size_t)k * N + n];
    __nv_bfloat16 h = __float2bfloat16(v);
    hi[i] = h;
    lo[i] = __float2bfloat16(v - __bfloat162float(h));
}

// ---------------------------------------------------------------------------
// mma.sync GEMM + alpha epilogue.
// C[M,N] = A[M,K] @ Bt^T (Bt is [N,K] K-major bf16 hi/lo), fp32 accum.
// Block: 256 threads = 8 warps; tile 128 rows x 64 cols (one head per block
// when HEADS==4). Warp tile 32x32. K consumed in 128-wide chunks.
// Smem rows padded to 68 words (stride 68 mod 32 = 4 -> conflict-free frags).
// ---------------------------------------------------------------------------
#define SM_AH 0
#define SM_AL 34816
#define SM_BH 69632
#define SM_BL 87040
#define SM_ALPHA 104448
#define SM_TOTAL 105472

template <int N, int K, int HEADS>
__global__ __launch_bounds__(256, 1)
void gemm_mma_kernel(const float* __restrict__ A,
                     const __nv_bfloat16* __restrict__ Bhi,
                     const __nv_bfloat16* __restrict__ Blo,
                     float* __restrict__ C,
                     const float* __restrict__ a_src,
                     const float* __restrict__ a_dst,
                     float* __restrict__ AS,
                     float* __restrict__ AD,
                     int M) {
    extern __shared__ char smem[];
    uint32_t* Ah = (uint32_t*)(smem + SM_AH);
    uint32_t* Al = (uint32_t*)(smem + SM_AL);
    uint32_t* Bh = (uint32_t*)(smem + SM_BH);
    uint32_t* Bl = (uint32_t*)(smem + SM_BL);
    float* alpha_s = (float*)(smem + SM_ALPHA);
    float* alpha_d = alpha_s + 128;

    const int tid = threadIdx.x;
    const int lane = tid & 31;
    const int wid = tid >> 5;
    const int warp_m = wid & 3;      // 4 m-slices of 32 rows
    const int warp_n = wid >> 2;     // 2 n-slices of 32 cols
    const int m0 = blockIdx.y * 128;
    const int col0 = blockIdx.x * 64;
    const int h = (HEADS == 4) ? blockIdx.x : 0;

    float acc[2][4][4];
    #pragma unroll
    for (int mt = 0; mt < 2; mt++)
        #pragma unroll
        for (int nt = 0; nt < 4; nt++)
            #pragma unroll
            for (int q = 0; q < 4; q++) acc[mt][nt][q] = 0.0f;

    for (int kc = 0; kc < K; kc += 128) {
        // ---- A chunk: fp32 -> split bf16 hi/lo into smem ----
        #pragma unroll
        for (int q = 0; q < 16; q++) {
            int idx = q * 256 + tid;           // 4096 float4 slots
            int r = idx >> 5;
            int c4 = idx & 31;
            int gr = m0 + r;
            float4 v = make_float4(0.f, 0.f, 0.f, 0.f);
            if (gr < M) v = *(const float4*)&A[(size_t)gr * K + kc + c4 * 4];
            __nv_bfloat162 hxy = __floats2bfloat162_rn(v.x, v.y);
            __nv_bfloat162 hzw = __floats2bfloat162_rn(v.z, v.w);
            float2 fxy = __bfloat1622float2(hxy);
            float2 fzw = __bfloat1622float2(hzw);
            __nv_bfloat162 lxy = __floats2bfloat162_rn(v.x - fxy.x, v.y - fxy.y);
            __nv_bfloat162 lzw = __floats2bfloat162_rn(v.z - fzw.x, v.w - fzw.y);
            int w = r * 68 + c4 * 2;
            Ah[w] = bf2u(hxy); Ah[w + 1] = bf2u(hzw);
            Al[w] = bf2u(lxy); Al[w + 1] = bf2u(lzw);
        }
        // ---- B chunk: preconverted bf16 hi/lo [N,K] ----
        #pragma unroll
        for (int q = 0; q < 4; q++) {
            int idx = q * 256 + tid;           // 1024 uint4 slots (8 bf16 each)
            int r = idx >> 4;
            int c8 = idx & 15;
            uint4 vh = *(const uint4*)&Bhi[(size_t)(col0 + r) * K + kc + c8 * 8];
            uint4 vl = *(const uint4*)&Blo[(size_t)(col0 + r) * K + kc + c8 * 8];
            *(uint4*)&Bh[r * 68 + c8 * 4] = vh;
            *(uint4*)&Bl[r * 68 + c8 * 4] = vl;
        }
        __syncthreads();

        // ---- MMA over 8 k16 steps ----
        #pragma unroll
        for (int ks = 0; ks < 8; ks++) {
            const int kw = ks * 8 + (lane & 3);
            uint32_t ah[2][4], al[2][4], bh[4][2], bl[4][2];
            #pragma unroll
            for (int mt = 0; mt < 2; mt++) {
                int r0 = warp_m * 32 + mt * 16 + (lane >> 2);
                ah[mt][0] = Ah[r0 * 68 + kw];
                ah[mt][1] = Ah[(r0 + 8) * 68 + kw];
                ah[mt][2] = Ah[r0 * 68 + kw + 4];
                ah[mt][3] = Ah[(r0 + 8) * 68 + kw + 4];
                al[mt][0] = Al[r0 * 68 + kw];
                al[mt][1] = Al[(r0 + 8) * 68 + kw];
                al[mt][2] = Al[r0 * 68 + kw + 4];
                al[mt][3] = Al[(r0 + 8) * 68 + kw + 4];
            }
            #pragma unroll
            for (int nt = 0; nt < 4; nt++) {
                int n0 = warp_n * 32 + nt * 8 + (lane >> 2);
                bh[nt][0] = Bh[n0 * 68 + kw];
                bh[nt][1] = Bh[n0 * 68 + kw + 4];
                bl[nt][0] = Bl[n0 * 68 + kw];
                bl[nt][1] = Bl[n0 * 68 + kw + 4];
            }
            #pragma unroll
            for (int mt = 0; mt < 2; mt++)
                #pragma unroll
                for (int nt = 0; nt < 4; nt++) {
                    mma16816(acc[mt][nt], ah[mt], bh[nt]);
                    mma16816(acc[mt][nt], ah[mt], bl[nt]);
                    mma16816(acc[mt][nt], al[mt], bh[nt]);
                }
        }
        __syncthreads();
    }

    // ---- epilogue: C store + alpha dot-products ----
    if (tid < 128) { alpha_s[tid] = 0.0f; alpha_d[tid] = 0.0f; }
    __syncthreads();

    float sp[4] = {0.f, 0.f, 0.f, 0.f};
    float dp[4] = {0.f, 0.f, 0.f, 0.f};
    #pragma unroll
    for (int mt = 0; mt < 2; mt++) {
        int r0 = warp_m * 32 + mt * 16 + (lane >> 2);
        #pragma unroll
        for (int nt = 0; nt < 4; nt++) {
            int c0 = warp_n * 32 + nt * 8 + (lane & 3) * 2;
            float* a4 = acc[mt][nt];
            int gr0 = m0 + r0;
            int gr1 = gr0 + 8;
            if (gr0 < M) *(float2*)&C[(size_t)gr0 * N + col0 + c0] = make_float2(a4[0], a4[1]);
            if (gr1 < M) *(float2*)&C[(size_t)gr1 * N + col0 + c0] = make_float2(a4[2], a4[3]);
            float s0 = __ldg(&a_src[h * 64 + c0]);
            float s1 = __ldg(&a_src[h * 64 + c0 + 1]);
            float d0 = __ldg(&a_dst[h * 64 + c0]);
            float d1 = __ldg(&a_dst[h * 64 + c0 + 1]);
            sp[mt * 2]     += a4[0] * s0 + a4[1] * s1;
            sp[mt * 2 + 1] += a4[2] * s0 + a4[3] * s1;
            dp[mt * 2]     += a4[0] * d0 + a4[1] * d1;
            dp[mt * 2 + 1] += a4[2] * d0 + a4[3] * d1;
        }
    }
    #pragma unroll
    for (int i = 0; i < 4; i++) {
        sp[i] += __shfl_xor_sync(0xffffffffu, sp[i], 1);
        sp[i] += __shfl_xor_sync(0xffffffffu, sp[i], 2);
        dp[i] += __shfl_xor_sync(0xffffffffu, dp[i], 1);
        dp[i] += __shfl_xor_sync(0xffffffffu, dp[i], 2);
    }
    if ((lane & 3) == 0) {
        int r0 = warp_m * 32 + (lane >> 2);
        atomicAdd(&alpha_s[r0],      sp[0]);
        atomicAdd(&alpha_s[r0 + 8],  sp[1]);
        atomicAdd(&alpha_s[r0 + 16], sp[2]);
        atomicAdd(&alpha_s[r0 + 24], sp[3]);
        atomicAdd(&alpha_d[r0],      dp[0]);
        atomicAdd(&alpha_d[r0 + 8],  dp[1]);
        atomicAdd(&alpha_d[r0 + 16], dp[2]);
        atomicAdd(&alpha_d[r0 + 24], dp[3]);
    }
    __syncthreads();
    if (tid < 128) {
        int gr = m0 + tid;
        if (gr < M) {
            AS[gr * HEADS + h] = alpha_s[tid];
            AD[gr * HEADS + h] = alpha_d[tid];
        }
    }
}

// ---------------------------------------------------------------------------
// CSR build (unchanged)
// ---------------------------------------------------------------------------
__global__ void deg_zero_kernel(int* __restrict__ deg, int n) {
    int i = blockIdx.x * blockDim.x + threadIdx.x;
    if (i < n) deg[i] = 0;
}

__global__ void hist_kernel(const int* __restrict__ ei, int* __restrict__ deg, int E) {
    int i = blockIdx.x * blockDim.x + threadIdx.x;
    if (i < E) atomicAdd(&deg[ei[E + i]], 1);
}

__global__ void scan_partial_kernel(const int* __restrict__ deg,
                                    int* __restrict__ part, int n) {
    __shared__ int red[256];
    const int t = threadIdx.x;
    const int base = blockIdx.x * SCAN_CHUNK + t * 16;
    int s = 0;
    #pragma unroll
    for (int q = 0; q < 16; q++) {
        int i = base + q;
        if (i < n) s += deg[i];
    }
    red[t] = s;
    __syncthreads();
    #pragma unroll
    for (int off = 128; off >= 1; off >>= 1) {
        if (t < off) red[t] += red[t + off];
        __syncthreads();
    }
    if (t == 0) part[blockIdx.x] = red[0];
}

__global__ void scan_root_kernel(int* __restrict__ part, int nb) {
    if (threadIdx.x == 0) {
        int run = 0;
        for (int i = 0; i < nb; i++) {
            int v = part[i];
            part[i] = run;
            run += v;
        }
        part[nb] = run;
    }
}

__global__ void scan_final_kernel(const int* __restrict__ deg,
                                  const int* __restrict__ part,
                                  int* __restrict__ rowptr,
                                  int* __restrict__ cur,
                                  int n, int nb) {
    __shared__ int thr[256];
    const int t = threadIdx.x;
    const int base = blockIdx.x * SCAN_CHUNK + t * 16;
    int s = 0;
    int dloc[16];
    #pragma unroll
    for (int q = 0; q < 16; q++) {
        int i = base + q;
        dloc[q] = (i < n) ? deg[i] : 0;
        s += dloc[q];
    }
    thr[t] = s;
    __syncthreads();
    #pragma unroll
    for (int off = 1; off < 256; off <<= 1) {
        int v = (t >= off) ? thr[t - off] : 0;
        __syncthreads();
        thr[t] += v;
        __syncthreads();
    }
    int offset = part[blockIdx.x] + ((t == 0) ? 0 : thr[t - 1]);
    #pragma unroll
    for (int q = 0; q < 16; q++) {
        int i = base + q;
        if (i < n) {
            rowptr[i] = offset;
            cur[i] = offset;
            offset += dloc[q];
        }
    }
    if (blockIdx.x == 0 && t == 0) rowptr[n] = part[nb];
}

__global__ void fill_kernel(const int* __restrict__ ei,
                            int* __restrict__ cur, int* __restrict__ ecol, int E) {
    int i = blockIdx.x * blockDim.x + threadIdx.x;
    if (i >= E) return;
    int s = ei[i];
    int d = ei[E + i];
    int slot = atomicAdd(&cur[d], 1);
    ecol[slot] = s;
}

// ---------------------------------------------------------------------------
// Fused GAT aggregation: warp per destination node (unchanged)
// ---------------------------------------------------------------------------
template <int HEADS, bool POOLING>
__global__ void gat_agg_kernel(const int* __restrict__ rowptr,
                               const int* __restrict__ ecol,
                               const float* __restrict__ AS,
                               const float* __restrict__ AD,
                               const float* __restrict__ H,
                               const float* __restrict__ bias,
                               float* __restrict__ OUT,
                               const int* __restrict__ batch,
                               float* __restrict__ POOL,
                               float* __restrict__ CNT,
                               int n) {
    const int warp = (blockIdx.x * blockDim.x + threadIdx.x) >> 5;
    const int lane = threadIdx.x & 31;
    if (warp >= n) return;
    const int d = warp;
    const int beg = rowptr[d];
    const int end = rowptr[d + 1];
    const int HD = HEADS * 64;

    float ad_d[HEADS], self_e[HEADS], mx[HEADS];
    #pragma unroll
    for (int h = 0; h < HEADS; h++) {
        ad_d[h] = AD[d * HEADS + h];
        self_e[h] = leaky(AS[d * HEADS + h] + ad_d[h]);
        mx[h] = self_e[h];
    }

    for (int j = beg + lane; j < end; j += 32) {
        int s = ecol[j];
        if (HEADS == 4) {
            float4 a4 = *(const float4*)&AS[s * 4];
            mx[0] = fmaxf(mx[0], leaky(a4.x + ad_d[0]));
            mx[1] = fmaxf(mx[1], leaky(a4.y + ad_d[1]));
            mx[2] = fmaxf(mx[2], leaky(a4.z + ad_d[2]));
            mx[3] = fmaxf(mx[3], leaky(a4.w + ad_d[3]));
        } else {
            mx[0] = fmaxf(mx[0], leaky(AS[s] + ad_d[0]));
        }
    }
    #pragma unroll
    for (int h = 0; h < HEADS; h++) {
        #pragma unroll
        for (int off = 16; off >= 1; off >>= 1)
            mx[h] = fmaxf(mx[h], __shfl_xor_sync(0xffffffffu, mx[h], off));
    }

    float den[HEADS];
    float acc[HEADS][2];
    #pragma unroll
    for (int h = 0; h < HEADS; h++) {
        float ex = __expf(self_e[h] - mx[h]);
        den[h] = ex;
        float2 hv = *(const float2*)&H[(size_t)d * HD + h * 64 + lane * 2];
        acc[h][0] = ex * hv.x;
        acc[h][1] = ex * hv.y;
    }
    for (int j = beg; j < end; j++) {
        int s = ecol[j];
        if (HEADS == 4) {
            float4 a4 = *(const float4*)&AS[s * 4];
            float e0 = __expf(leaky(a4.x + ad_d[0]) - mx[0]);
            float e1 = __expf(leaky(a4.y + ad_d[1]) - mx[1]);
            float e2 = __expf(leaky(a4.z + ad_d[2]) - mx[2]);
            float e3 = __expf(leaky(a4.w + ad_d[3]) - mx[3]);
            den[0] += e0; den[1] += e1; den[2] += e2; den[3] += e3;
            const float* hr = &H[(size_t)s * 256 + lane * 2];
            float2 h0 = *(const float2*)&hr[0];
            float2 h1 = *(const float2*)&hr[64];
            float2 h2 = *(const float2*)&hr[128];
            float2 h3 = *(const float2*)&hr[192];
            acc[0][0] += e0 * h0.x; acc[0][1] += e0 * h0.y;
            acc[1][0] += e1 * h1.x; acc[1][1] += e1 * h1.y;
            acc[2][0] += e2 * h2.x; acc[2][1] += e2 * h2.y;
            acc[3][0] += e3 * h3.x; acc[3][1] += e3 * h3.y;
        } else {
            float ex = __expf(leaky(AS[s] + ad_d[0]) - mx[0]);
            den[0] += ex;
            float2 hv = *(const float2*)&H[(size_t)s * 64 + lane * 2];
            acc[0][0] += ex * hv.x;
            acc[0][1] += ex * hv.y;
        }
    }

    #pragma unroll
    for (int h = 0; h < HEADS; h++) {
        float inv = 1.0f / (den[h] + 1e-16f);
        float v0 = acc[h][0] * inv + bias[h * 64 + lane * 2 + 0];
        float v1 = acc[h][1] * inv + bias[h * 64 + lane * 2 + 1];
        v0 = v0 > 0.0f ? v0 : (__expf(v0) - 1.0f);
        v1 = v1 > 0.0f ? v1 : (__expf(v1) - 1.0f);
        if (POOLING) {
            int g = batch[d];
            atomicAdd(&POOL[g * 64 + lane * 2 + 0], v0);
            atomicAdd(&POOL[g * 64 + lane * 2 + 1], v1);
            if (lane == 0 && h == 0) atomicAdd(&CNT[g], 1.0f);
        } else {
            float2 ov = make_float2(v0, v1);
            *(float2*)&OUT[(size_t)d * HD + h * 64 + lane * 2] = ov;
        }
    }
}

__global__ void pool_zero_kernel(float* __restrict__ POOL, float* __restrict__ CNT) {
    int i = blockIdx.x * blockDim.x + threadIdx.x;
    if (i < 2 * GNUM * 64) POOL[i] = 0.0f;
    if (i < 2 * GNUM) CNT[i] = 0.0f;
}

__global__ void final_write_kernel(const float* __restrict__ POOL,
                                   const float* __restrict__ CNT,
                                   float* __restrict__ out) {
    int i = blockIdx.x * blockDim.x + threadIdx.x;
    if (i >= 2 * GNUM * 64) return;
    float c = CNT[i >> 6];
    out[i] = POOL[i] / fmaxf(c, 1.0f);
}

// ---------------------------------------------------------------------------
// Launch
// ---------------------------------------------------------------------------
extern "C" void kernel_launch(void* const* d_in, const int* in_sizes, int n_in,
                              void* d_out, int out_size) {
    const float* x1  = (const float*)d_in[0];
    const int*   ei1 = (const int*)d_in[1];
    const int*   bt1 = (const int*)d_in[2];
    const float* x2  = (const float*)d_in[3];
    const int*   ei2 = (const int*)d_in[4];
    const int*   bt2 = (const int*)d_in[5];
    const float* W1  = (const float*)d_in[6];
    const float* as1 = (const float*)d_in[7];
    const float* ad1 = (const float*)d_in[8];
    const float* b1  = (const float*)d_in[9];
    const float* W2  = (const float*)d_in[10];
    const float* as2 = (const float*)d_in[11];
    const float* ad2 = (const float*)d_in[12];
    const float* b2  = (const float*)d_in[13];

    const int n = in_sizes[0] / 128;
    const int e = in_sizes[1] / 2;
    const int nb = cdiv(n, SCAN_CHUNK);

    float *H, *OUT, *H2, *AS, *AD, *POOL, *CNT;
    int *DEG, *ROWPTR, *CUR, *ECOL, *PART;
    __nv_bfloat16 *W1TH, *W1TL, *W2TH, *W2TL;
    cudaGetSymbolAddress((void**)&H,      g_H);
    cudaGetSymbolAddress((void**)&OUT,    g_OUT);
    cudaGetSymbolAddress((void**)&H2,     g_H2);
    cudaGetSymbolAddress((void**)&AS,     g_AS);
    cudaGetSymbolAddress((void**)&AD,     g_AD);
    cudaGetSymbolAddress((void**)&DEG,    g_DEG);
    cudaGetSymbolAddress((void**)&ROWPTR, g_ROWPTR);
    cudaGetSymbolAddress((void**)&CUR,    g_CUR);
    cudaGetSymbolAddress((void**)&ECOL,   g_ECOL);
    cudaGetSymbolAddress((void**)&PART,   g_PART);
    cudaGetSymbolAddress((void**)&POOL,   g_POOL);
    cudaGetSymbolAddress((void**)&CNT,    g_CNT);
    cudaGetSymbolAddress((void**)&W1TH,   g_W1T_HI);
    cudaGetSymbolAddress((void**)&W1TL,   g_W1T_LO);
    cudaGetSymbolAddress((void**)&W2TH,   g_W2T_HI);
    cudaGetSymbolAddress((void**)&W2TL,   g_W2T_LO);

    cudaFuncSetAttribute(gemm_mma_kernel<256, 128, 4>,
                         cudaFuncAttributeMaxDynamicSharedMemorySize, SM_TOTAL);
    cudaFuncSetAttribute(gemm_mma_kernel<64, 256, 1>,
                         cudaFuncAttributeMaxDynamicSharedMemorySize, SM_TOTAL);

    pool_zero_kernel<<<cdiv(2 * GNUM * 64, 256), 256>>>(POOL, CNT);
    prep_w_kernel<<<cdiv(256 * 128, 256), 256>>>(W1, W1TH, W1TL, 128, 256);
    prep_w_kernel<<<cdiv(64 * 256, 256), 256>>>(W2, W2TH, W2TL, 256, 64);

    for (int g = 0; g < 2; g++) {
        const float* x  = g ? x2  : x1;
        const int*   ei = g ? ei2 : ei1;
        const int*   bt = g ? bt2 : bt1;

        // CSR build (dst-sorted)
        deg_zero_kernel<<<cdiv(n, 256), 256>>>(DEG, n);
        hist_kernel<<<cdiv(e, 256), 256>>>(ei, DEG, e);
        scan_partial_kernel<<<nb, 256>>>(DEG, PART, n);
        scan_root_kernel<<<1, 32>>>(PART, nb);
        scan_final_kernel<<<nb, 256>>>(DEG, PART, ROWPTR, CUR, n, nb);
        fill_kernel<<<cdiv(e, 256), 256>>>(ei, CUR, ECOL, e);

        // conv1: GAT(128 -> 64, heads=4)  [mma GEMM + alpha epilogue]
        {
            dim3 grid(4, cdiv(n, 128));
            gemm_mma_kernel<256, 128, 4><<<grid, 256, SM_TOTAL>>>(
                x, W1TH, W1TL, H, as1, ad1, AS, AD, n);
        }
        gat_agg_kernel<4, false><<<cdiv(n, 8), 256>>>(
            ROWPTR, ECOL, AS, AD, H, b1, OUT, nullptr, nullptr, nullptr, n);

        // conv2: GAT(256 -> 64, heads=1), fused pooling
        {
            dim3 grid(1, cdiv(n, 128));
            gemm_mma_kernel<64, 256, 1><<<grid, 256, SM_TOTAL>>>(
                OUT, W2TH, W2TL, H2, as2, ad2, AS, AD, n);
        }
        gat_agg_kernel<1, true><<<cdiv(n, 8), 256>>>(
            ROWPTR, ECOL, AS, AD, H2, b2, nullptr, bt,
            POOL + g * GNUM * 64, CNT + g * GNUM, n);
    }

    final_write_kernel<<<cdiv(2 * GNUM * 64, 256), 256>>>(POOL, CNT, (float*)d_out);
}